// round 3
// baseline (speedup 1.0000x reference)
#include <cuda_runtime.h>

// Problem constants (fixed by the reference setup)
#define NB1 64
#define NS1 128
#define NB2 64
#define NS2 128
#define NH  768

// Normalized inputs (static device scratch; no runtime allocation)
__device__ float g_x1n[NB1 * NS1 * NH];
__device__ float g_x2n[NB2 * NS2 * NH];

// ---------------------------------------------------------------------------
// Kernel 1: L2-normalize every row of x1 and x2.
// grid = (8192, 2), block = 256. Each thread handles 3 elements (768/256).
// ---------------------------------------------------------------------------
__global__ void normalize_kernel(const float* __restrict__ x1,
                                 const float* __restrict__ x2) {
    const int row = blockIdx.x;
    const float* src = (blockIdx.y == 0) ? x1 : x2;
    float* dst       = (blockIdx.y == 0) ? g_x1n : g_x2n;

    const float* p = src + (size_t)row * NH;
    float v[3];
    float s = 0.f;
#pragma unroll
    for (int i = 0; i < 3; i++) {
        v[i] = p[threadIdx.x + i * 256];
        s += v[i] * v[i];
    }
    // warp reduce
#pragma unroll
    for (int o = 16; o > 0; o >>= 1) s += __shfl_xor_sync(0xffffffffu, s, o);
    __shared__ float red[8];
    if ((threadIdx.x & 31) == 0) red[threadIdx.x >> 5] = s;
    __syncthreads();
    float tot = 0.f;
#pragma unroll
    for (int i = 0; i < 8; i++) tot += red[i];
    const float inv = rsqrtf(tot);

    float* d = dst + (size_t)row * NH;
#pragma unroll
    for (int i = 0; i < 3; i++) d[threadIdx.x + i * 256] = v[i] * inv;
}

// ---------------------------------------------------------------------------
// Kernel 2: one CTA per (a,b) pair.
//   - 128x128x768 fp32 GEMM on normalized rows (cosines)
//   - fused masked row-max / col-max, masked means, final scalar
// Block: 256 threads = 16x16 (tx, ty), each thread owns an 8x8 micro-tile
// with STRIDED rows (ty + 16*i) and cols (tx + 16*j).
// Tile loads use a register-prefetch pipeline: the NEXT k-tile's global
// loads issue before the CURRENT tile's compute, hiding L2/DRAM latency.
// ---------------------------------------------------------------------------
#define KT 32
#define NTILES (NH / KT)  // 24
#define PADF 36  // 32 + 4 floats row pad: 9 float4 per row -> odd f4 stride

__global__ __launch_bounds__(256, 1)
void pair_kernel(const int* __restrict__ mask1,
                 const int* __restrict__ mask2,
                 float* __restrict__ out) {
    const int a = blockIdx.x;
    const int b = blockIdx.y;
    const int tid = threadIdx.x;
    const int tx = tid & 15;
    const int ty = tid >> 4;

    __shared__ union {
        struct { float A[128][PADF]; float B[128][PADF]; } t;   // 36864 B
        struct { float rowp[128][16]; float colp[128][16]; } r; // 16384 B
    } sm;
    __shared__ float m1v[128];  // 0.0 if valid, -2e30 if masked (additive bias)
    __shared__ float m2v[128];
    __shared__ float m1raw[128];  // 1.0 / 0.0
    __shared__ float m2raw[128];
    __shared__ float rbuf[8];

    // Load masks: raw 0/1 and additive bias form
    if (tid < 128) {
        const float m = (float)mask1[a * NS1 + tid];
        m1raw[tid] = m;
        m1v[tid] = (m != 0.f) ? 0.f : -2e30f;
    } else {
        const int r = tid - 128;
        const float m = (float)mask2[b * NS2 + r];
        m2raw[r] = m;
        m2v[r] = (m != 0.f) ? 0.f : -2e30f;
    }

    const float* Abase = g_x1n + (size_t)a * NS1 * NH;
    const float* Bbase = g_x2n + (size_t)b * NS2 * NH;

    float acc[8][8];
#pragma unroll
    for (int i = 0; i < 8; i++)
#pragma unroll
        for (int j = 0; j < 8; j++) acc[i][j] = 0.f;

    const int lm = tid >> 3;  // 0..31 : row within 32-row load pass
    const int lk = tid & 7;   // 0..7  : float4 index within 32-float k-tile

    // ---- prefetch pipeline state: 4 passes x (A,B) float4 per thread ----
    float4 pva[4], pvb[4];

    // Preload tile 0 into registers
#pragma unroll
    for (int p = 0; p < 4; p++) {
        const int m = lm + 32 * p;
        pva[p] = *(const float4*)(Abase + (size_t)m * NH + lk * 4);
        pvb[p] = *(const float4*)(Bbase + (size_t)m * NH + lk * 4);
    }
    // Store tile 0 to smem
#pragma unroll
    for (int p = 0; p < 4; p++) {
        const int m = lm + 32 * p;
        *(float4*)(&sm.t.A[m][lk * 4]) = pva[p];
        *(float4*)(&sm.t.B[m][lk * 4]) = pvb[p];
    }
    __syncthreads();  // tile 0 visible (also orders the mask stores)

    for (int t = 0; t < NTILES; t++) {
        // Issue next tile's global loads early (latency hidden by compute)
        if (t + 1 < NTILES) {
            const int k0 = (t + 1) * KT;
#pragma unroll
            for (int p = 0; p < 4; p++) {
                const int m = lm + 32 * p;
                pva[p] = *(const float4*)(Abase + (size_t)m * NH + k0 + lk * 4);
                pvb[p] = *(const float4*)(Bbase + (size_t)m * NH + k0 + lk * 4);
            }
        }

        // Compute on the current smem tile
#pragma unroll 2
        for (int kk = 0; kk < KT; kk += 4) {
            float4 a4[8], b4[8];
#pragma unroll
            for (int i = 0; i < 8; i++)
                a4[i] = *(const float4*)(&sm.t.A[ty + 16 * i][kk]);
#pragma unroll
            for (int j = 0; j < 8; j++)
                b4[j] = *(const float4*)(&sm.t.B[tx + 16 * j][kk]);
#pragma unroll
            for (int i = 0; i < 8; i++)
#pragma unroll
                for (int j = 0; j < 8; j++) {
                    acc[i][j] += a4[i].x * b4[j].x;
                    acc[i][j] += a4[i].y * b4[j].y;
                    acc[i][j] += a4[i].z * b4[j].z;
                    acc[i][j] += a4[i].w * b4[j].w;
                }
        }
        __syncthreads();  // everyone done READING current tile

        if (t + 1 < NTILES) {
#pragma unroll
            for (int p = 0; p < 4; p++) {
                const int m = lm + 32 * p;
                *(float4*)(&sm.t.A[m][lk * 4]) = pva[p];
                *(float4*)(&sm.t.B[m][lk * 4]) = pvb[p];
            }
            __syncthreads();  // next tile visible
        }
    }
    // last loop iteration ended with a sync; union reuse below is safe

    // --- per-thread partial maxes over this thread's 8x8 tile (branch-free:
    //     invalid entries get a -2e30 additive bias; cosines are in [-1,1]) ---
    float mb2[8], mb1[8];
#pragma unroll
    for (int j = 0; j < 8; j++) mb2[j] = m2v[tx + 16 * j];
#pragma unroll
    for (int i = 0; i < 8; i++) mb1[i] = m1v[ty + 16 * i];

#pragma unroll
    for (int i = 0; i < 8; i++) {
        float rmax = -3e30f;
#pragma unroll
        for (int j = 0; j < 8; j++) rmax = fmaxf(rmax, acc[i][j] + mb2[j]);
        sm.r.rowp[ty + 16 * i][tx] = rmax;
    }
#pragma unroll
    for (int j = 0; j < 8; j++) {
        float cmax = -3e30f;
#pragma unroll
        for (int i = 0; i < 8; i++) cmax = fmaxf(cmax, acc[i][j] + mb1[i]);
        sm.r.colp[tx + 16 * j][ty] = cmax;
    }
    __syncthreads();

    // --- finish maxes (16 partials each), masked mean contributions ---
    float val;
    {
        const int r = tid & 127;
        const bool isRow = (tid < 128);
        float m = isRow ? sm.r.rowp[r][0] : sm.r.colp[r][0];
#pragma unroll
        for (int q = 1; q < 16; q++)
            m = fmaxf(m, isRow ? sm.r.rowp[r][q] : sm.r.colp[r][q]);
        const float* mv = isRow ? m1raw : m2raw;
        float cnt = 0.f;
#pragma unroll 8
        for (int q = 0; q < 128; q++) cnt += mv[q];
        // mv[r]==0 -> contribute 0; else m/cnt * 0.5
        val = mv[r] * (m / cnt) * 0.5f;
    }

    // --- block sum of 256 contributions -> (s1 + s2) / 2 ---
#pragma unroll
    for (int o = 16; o > 0; o >>= 1) val += __shfl_xor_sync(0xffffffffu, val, o);
    if ((tid & 31) == 0) rbuf[tid >> 5] = val;
    __syncthreads();
    if (tid == 0) {
        float s = 0.f;
#pragma unroll
        for (int i = 0; i < 8; i++) s += rbuf[i];
        out[a * NB2 + b] = s;
    }
}

// ---------------------------------------------------------------------------
// Launch: inputs are x1 (f32), mask1 (i32), x2 (f32), mask2 (i32); out f32[4096]
// ---------------------------------------------------------------------------
extern "C" void kernel_launch(void* const* d_in, const int* in_sizes, int n_in,
                              void* d_out, int out_size) {
    const float* x1 = (const float*)d_in[0];
    const int* mask1 = (const int*)d_in[1];
    const float* x2 = (const float*)d_in[2];
    const int* mask2 = (const int*)d_in[3];
    float* out = (float*)d_out;

    normalize_kernel<<<dim3(NB1 * NS1, 2), 256>>>(x1, x2);
    pair_kernel<<<dim3(NB1, NB2), 256>>>(mask1, mask2, out);
}

// round 14
// speedup vs baseline: 3.3070x; 3.3070x over previous
#include <cuda_runtime.h>
#include <cstdint>

#define NB1 64
#define NS1 128
#define NB2 64
#define NS2 128
#define NH  768

// Normalized (and tf32-RNA-rounded) inputs
__device__ float g_x1n[NB1 * NS1 * NH];
__device__ float g_x2n[NB2 * NS2 * NH];

// ---------------------------------------------------------------------------
// Kernel 1: L2-normalize rows, round to tf32 (RNA) so HW tf32 MMA is exact.
// ---------------------------------------------------------------------------
__global__ void normalize_kernel(const float* __restrict__ x1,
                                 const float* __restrict__ x2) {
    const int row = blockIdx.x;
    const float* src = (blockIdx.y == 0) ? x1 : x2;
    float* dst       = (blockIdx.y == 0) ? g_x1n : g_x2n;

    const float* p = src + (size_t)row * NH;
    float v[3];
    float s = 0.f;
#pragma unroll
    for (int i = 0; i < 3; i++) {
        v[i] = p[threadIdx.x + i * 256];
        s += v[i] * v[i];
    }
#pragma unroll
    for (int o = 16; o > 0; o >>= 1) s += __shfl_xor_sync(0xffffffffu, s, o);
    __shared__ float red[8];
    if ((threadIdx.x & 31) == 0) red[threadIdx.x >> 5] = s;
    __syncthreads();
    float tot = 0.f;
#pragma unroll
    for (int i = 0; i < 8; i++) tot += red[i];
    const float inv = rsqrtf(tot);

    float* d = dst + (size_t)row * NH;
#pragma unroll
    for (int i = 0; i < 3; i++) {
        float w = v[i] * inv;
        uint32_t r;
        asm("cvt.rna.tf32.f32 %0, %1;" : "=r"(r) : "f"(w));
        d[threadIdx.x + i * 256] = __uint_as_float(r);
    }
}

// ---------------------------------------------------------------------------
// Kernel 2: one CTA per (a,b) pair. Warp-level tf32 mma.sync GEMM
// (128x128x768) + fused masked row/col max + masked means.
//
// 8 warps in a 2x4 grid: warp (wr, wc) computes rows [wr*64, wr*64+64),
// cols [wc*32, wc*32+32) using 4x4 m16n8k8 atoms.
// A/B staged in smem (KT=32, stride 36 -> conflict-free fragment LDS),
// global loads register-prefetched one tile ahead (proven R3 pipeline).
// ---------------------------------------------------------------------------
#define KT 32
#define NTILES (NH / KT)  // 24
#define PADF 36

__device__ __forceinline__ void mma_tf32(float* d, uint32_t a0, uint32_t a1,
                                         uint32_t a2, uint32_t a3,
                                         uint32_t b0, uint32_t b1) {
    asm volatile(
        "mma.sync.aligned.m16n8k8.row.col.f32.tf32.tf32.f32 "
        "{%0,%1,%2,%3}, {%4,%5,%6,%7}, {%8,%9}, {%0,%1,%2,%3};"
        : "+f"(d[0]), "+f"(d[1]), "+f"(d[2]), "+f"(d[3])
        : "r"(a0), "r"(a1), "r"(a2), "r"(a3), "r"(b0), "r"(b1));
}

__device__ __forceinline__ float shfl_max(float v, int mask) {
    return fmaxf(v, __shfl_xor_sync(0xffffffffu, v, mask));
}

__global__ __launch_bounds__(256, 1)
void pair_kernel(const int* __restrict__ mask1,
                 const int* __restrict__ mask2,
                 float* __restrict__ out) {
    const int a = blockIdx.x;
    const int b = blockIdx.y;
    const int tid = threadIdx.x;
    const int lane = tid & 31;
    const int warp = tid >> 5;
    const int wr = warp >> 2;       // 0..1  : 64-row block
    const int wc = warp & 3;        // 0..3  : 32-col block
    const int g = lane >> 2;        // groupID 0..7
    const int tg = lane & 3;        // threadID-in-group 0..3

    __shared__ float As[128][PADF];
    __shared__ float Bs[128][PADF];
    __shared__ float rowp[128][4];
    __shared__ float colp[128][2];
    __shared__ float m1raw[128], m2raw[128], m1b[128], m2b[128];
    __shared__ float rbuf[8];

    // masks: raw 0/1 + additive bias form
    if (tid < 128) {
        const float m = (float)mask1[a * NS1 + tid];
        m1raw[tid] = m;
        m1b[tid] = (m != 0.f) ? 0.f : -2e30f;
    } else {
        const int r = tid - 128;
        const float m = (float)mask2[b * NS2 + r];
        m2raw[r] = m;
        m2b[r] = (m != 0.f) ? 0.f : -2e30f;
    }

    const float* Abase = g_x1n + (size_t)a * NS1 * NH;
    const float* Bbase = g_x2n + (size_t)b * NS2 * NH;

    float acc[4][4][4];
#pragma unroll
    for (int i = 0; i < 4; i++)
#pragma unroll
        for (int j = 0; j < 4; j++)
#pragma unroll
            for (int q = 0; q < 4; q++) acc[i][j][q] = 0.f;

    const int lm = tid >> 3;  // 0..31
    const int lk = tid & 7;   // 0..7

    float4 pva[4], pvb[4];
#pragma unroll
    for (int p = 0; p < 4; p++) {
        const int m = lm + 32 * p;
        pva[p] = *(const float4*)(Abase + (size_t)m * NH + lk * 4);
        pvb[p] = *(const float4*)(Bbase + (size_t)m * NH + lk * 4);
    }
#pragma unroll
    for (int p = 0; p < 4; p++) {
        const int m = lm + 32 * p;
        *(float4*)(&As[m][lk * 4]) = pva[p];
        *(float4*)(&Bs[m][lk * 4]) = pvb[p];
    }
    __syncthreads();  // tile 0 visible (also orders mask stores)

    for (int t = 0; t < NTILES; t++) {
        if (t + 1 < NTILES) {
            const int k0 = (t + 1) * KT;
#pragma unroll
            for (int p = 0; p < 4; p++) {
                const int m = lm + 32 * p;
                pva[p] = *(const float4*)(Abase + (size_t)m * NH + k0 + lk * 4);
                pvb[p] = *(const float4*)(Bbase + (size_t)m * NH + k0 + lk * 4);
            }
        }

        // compute on current tile: 4 k-steps of 8
#pragma unroll
        for (int ks = 0; ks < KT; ks += 8) {
            uint32_t bf[4][2];
#pragma unroll
            for (int j = 0; j < 4; j++) {
                const float* bp = &Bs[wc * 32 + j * 8 + g][ks + tg];
                bf[j][0] = __float_as_uint(bp[0]);
                bf[j][1] = __float_as_uint(bp[4]);
            }
#pragma unroll
            for (int i = 0; i < 4; i++) {
                const float* ap0 = &As[wr * 64 + i * 16 + g][ks + tg];
                const float* ap1 = ap0 + 8 * PADF;
                const uint32_t a0 = __float_as_uint(ap0[0]);
                const uint32_t a1 = __float_as_uint(ap1[0]);
                const uint32_t a2 = __float_as_uint(ap0[4]);
                const uint32_t a3 = __float_as_uint(ap1[4]);
#pragma unroll
                for (int j = 0; j < 4; j++)
                    mma_tf32(acc[i][j], a0, a1, a2, a3, bf[j][0], bf[j][1]);
            }
        }
        __syncthreads();  // done reading current tile

        if (t + 1 < NTILES) {
#pragma unroll
            for (int p = 0; p < 4; p++) {
                const int m = lm + 32 * p;
                *(float4*)(&As[m][lk * 4]) = pva[p];
                *(float4*)(&Bs[m][lk * 4]) = pvb[p];
            }
            __syncthreads();
        }
    }

    // ---- fused masked row-max (over cols, bias m2b) ----
    // D frag mapping: d0:(g, 2tg) d1:(g, 2tg+1) d2:(g+8, 2tg) d3:(g+8, 2tg+1)
#pragma unroll
    for (int i = 0; i < 4; i++) {
        float r0 = -3e30f, r1 = -3e30f;
#pragma unroll
        for (int j = 0; j < 4; j++) {
            const int c0 = wc * 32 + j * 8 + 2 * tg;
            const float b0 = m2b[c0], b1 = m2b[c0 + 1];
            r0 = fmaxf(r0, fmaxf(acc[i][j][0] + b0, acc[i][j][1] + b1));
            r1 = fmaxf(r1, fmaxf(acc[i][j][2] + b0, acc[i][j][3] + b1));
        }
        r0 = shfl_max(shfl_max(r0, 1), 2);  // reduce over tg lanes
        r1 = shfl_max(shfl_max(r1, 1), 2);
        if (tg == 0) {
            rowp[wr * 64 + i * 16 + g][wc] = r0;
            rowp[wr * 64 + i * 16 + g + 8][wc] = r1;
        }
    }

    // ---- fused masked col-max (over rows, bias m1b) ----
#pragma unroll
    for (int j = 0; j < 4; j++) {
        float c0m = -3e30f, c1m = -3e30f;
#pragma unroll
        for (int i = 0; i < 4; i++) {
            const int r0i = wr * 64 + i * 16 + g;
            const float bb0 = m1b[r0i], bb1 = m1b[r0i + 8];
            c0m = fmaxf(c0m, fmaxf(acc[i][j][0] + bb0, acc[i][j][2] + bb1));
            c1m = fmaxf(c1m, fmaxf(acc[i][j][1] + bb0, acc[i][j][3] + bb1));
        }
        c0m = shfl_max(shfl_max(shfl_max(c0m, 4), 8), 16);  // reduce over g lanes
        c1m = shfl_max(shfl_max(shfl_max(c1m, 4), 8), 16);
        if (g == 0) {
            colp[wc * 32 + j * 8 + 2 * tg][wr] = c0m;
            colp[wc * 32 + j * 8 + 2 * tg + 1][wr] = c1m;
        }
    }
    __syncthreads();

    // ---- finish maxes, masked mean contributions ----
    float val;
    {
        const int r = tid & 127;
        float mx;
        const float* mv;
        if (tid < 128) {
            mx = fmaxf(fmaxf(rowp[r][0], rowp[r][1]),
                       fmaxf(rowp[r][2], rowp[r][3]));
            mv = m1raw;
        } else {
            mx = fmaxf(colp[r][0], colp[r][1]);
            mv = m2raw;
        }
        float cnt = 0.f;
#pragma unroll 8
        for (int q = 0; q < 128; q++) cnt += mv[q];
        val = mv[r] * (mx / cnt) * 0.5f;
    }

#pragma unroll
    for (int o = 16; o > 0; o >>= 1) val += __shfl_xor_sync(0xffffffffu, val, o);
    if ((tid & 31) == 0) rbuf[tid >> 5] = val;
    __syncthreads();
    if (tid == 0) {
        float s = 0.f;
#pragma unroll
        for (int i = 0; i < 8; i++) s += rbuf[i];
        out[a * NB2 + b] = s;
    }
}

// ---------------------------------------------------------------------------
extern "C" void kernel_launch(void* const* d_in, const int* in_sizes, int n_in,
                              void* d_out, int out_size) {
    const float* x1 = (const float*)d_in[0];
    const int* mask1 = (const int*)d_in[1];
    const float* x2 = (const float*)d_in[2];
    const int* mask2 = (const int*)d_in[3];
    float* out = (float*)d_out;

    normalize_kernel<<<dim3(NB1 * NS1, 2), 256>>>(x1, x2);
    pair_kernel<<<dim3(NB1, NB2), 256>>>(mask1, mask2, out);
}

// round 15
// speedup vs baseline: 3.8652x; 1.1688x over previous
#include <cuda_runtime.h>
#include <cstdint>

#define NB1 64
#define NS1 128
#define NB2 64
#define NS2 128
#define NH  768

// Normalized (and tf32-RNA-rounded) inputs
__device__ float g_x1n[NB1 * NS1 * NH];
__device__ float g_x2n[NB2 * NS2 * NH];

// ---------------------------------------------------------------------------
// Kernel 1: L2-normalize rows, round to tf32 (RNA) so HW tf32 MMA is exact.
// ---------------------------------------------------------------------------
__global__ void normalize_kernel(const float* __restrict__ x1,
                                 const float* __restrict__ x2) {
    const int row = blockIdx.x;
    const float* src = (blockIdx.y == 0) ? x1 : x2;
    float* dst       = (blockIdx.y == 0) ? g_x1n : g_x2n;

    const float* p = src + (size_t)row * NH;
    float v[3];
    float s = 0.f;
#pragma unroll
    for (int i = 0; i < 3; i++) {
        v[i] = p[threadIdx.x + i * 256];
        s += v[i] * v[i];
    }
#pragma unroll
    for (int o = 16; o > 0; o >>= 1) s += __shfl_xor_sync(0xffffffffu, s, o);
    __shared__ float red[8];
    if ((threadIdx.x & 31) == 0) red[threadIdx.x >> 5] = s;
    __syncthreads();
    float tot = 0.f;
#pragma unroll
    for (int i = 0; i < 8; i++) tot += red[i];
    const float inv = rsqrtf(tot);

    float* d = dst + (size_t)row * NH;
#pragma unroll
    for (int i = 0; i < 3; i++) {
        float w = v[i] * inv;
        uint32_t r;
        asm("cvt.rna.tf32.f32 %0, %1;" : "=r"(r) : "f"(w));
        d[threadIdx.x + i * 256] = __uint_as_float(r);
    }
}

// ---------------------------------------------------------------------------
// Kernel 2: one CTA per (a,b) pair. Warp-level tf32 mma.sync GEMM + fused
// masked row/col max + masked means. Same 64x32 warp tiles as R14 (keeps
// per-output LDS bytes), but:
//  - cp.async (LDGSTS) 2-stage double buffer replaces register prefetch
//    (-32 regs), dynamic smem.
//  - __launch_bounds__(256, 2): target 2 CTAs/SM (16 warps) to hide
//    LDS/HMMA/barrier latency (R14 showed latency-bound: nothing saturated).
// ---------------------------------------------------------------------------
#define KT 32
#define NTILES (NH / KT)  // 24
#define PADF 36
#define MAT_BYTES (128 * PADF * 4)      // 18432 per matrix per stage
#define STAGE_BYTES (2 * MAT_BYTES)     // A+B per stage = 36864
#define OFF_AUX (2 * STAGE_BYTES)       // 73728
#define DSMEM_TOTAL (OFF_AUX + 2304)    // aux: 4x512 masks + rbuf + pad

__device__ __forceinline__ uint32_t smem_u32(const void* p) {
    uint32_t a;
    asm("{ .reg .u64 t; cvta.to.shared.u64 t, %1; cvt.u32.u64 %0, t; }"
        : "=r"(a) : "l"(p));
    return a;
}
__device__ __forceinline__ void cp16(uint32_t dst, const void* src) {
    asm volatile("cp.async.cg.shared.global [%0], [%1], 16;"
                 :: "r"(dst), "l"(src) : "memory");
}
__device__ __forceinline__ void cp_commit() {
    asm volatile("cp.async.commit_group;" ::: "memory");
}
template <int N>
__device__ __forceinline__ void cp_wait() {
    asm volatile("cp.async.wait_group %0;" :: "n"(N) : "memory");
}

__device__ __forceinline__ void mma_tf32(float* d, uint32_t a0, uint32_t a1,
                                         uint32_t a2, uint32_t a3,
                                         uint32_t b0, uint32_t b1) {
    asm volatile(
        "mma.sync.aligned.m16n8k8.row.col.f32.tf32.tf32.f32 "
        "{%0,%1,%2,%3}, {%4,%5,%6,%7}, {%8,%9}, {%0,%1,%2,%3};"
        : "+f"(d[0]), "+f"(d[1]), "+f"(d[2]), "+f"(d[3])
        : "r"(a0), "r"(a1), "r"(a2), "r"(a3), "r"(b0), "r"(b1));
}

__device__ __forceinline__ float shfl_max(float v, int mask) {
    return fmaxf(v, __shfl_xor_sync(0xffffffffu, v, mask));
}

__global__ __launch_bounds__(256, 2)
void pair_kernel(const int* __restrict__ mask1,
                 const int* __restrict__ mask2,
                 float* __restrict__ out) {
    extern __shared__ __align__(16) char dsm[];
    const int a = blockIdx.x;
    const int b = blockIdx.y;
    const int tid = threadIdx.x;
    const int lane = tid & 31;
    const int warp = tid >> 5;
    const int wr = warp >> 2;       // 0..1  : 64-row block
    const int wc = warp & 3;        // 0..3  : 32-col block
    const int g = lane >> 2;        // groupID 0..7
    const int tg = lane & 3;        // threadID-in-group 0..3

    const uint32_t smem_base = smem_u32(dsm);

    // aux region (persists through GEMM)
    float* m1raw = (float*)(dsm + OFF_AUX);
    float* m2raw = (float*)(dsm + OFF_AUX + 512);
    float* m1b   = (float*)(dsm + OFF_AUX + 1024);
    float* m2b   = (float*)(dsm + OFF_AUX + 1536);
    float* rbuf  = (float*)(dsm + OFF_AUX + 2048);
    // epilogue scratch aliases stage 0 (safe: last GEMM read of stage0 is
    // tile t=22; rowp/colp written after tile 23's trailing sync)
    float* rowp = (float*)dsm;            // [128][4]
    float* colp = (float*)(dsm + 2048);   // [128][2]

    // masks: raw 0/1 + additive bias form
    if (tid < 128) {
        const float m = (float)mask1[a * NS1 + tid];
        m1raw[tid] = m;
        m1b[tid] = (m != 0.f) ? 0.f : -2e30f;
    } else {
        const int r = tid - 128;
        const float m = (float)mask2[b * NS2 + r];
        m2raw[r] = m;
        m2b[r] = (m != 0.f) ? 0.f : -2e30f;
    }

    const float* Abase = g_x1n + (size_t)a * NS1 * NH;
    const float* Bbase = g_x2n + (size_t)b * NS2 * NH;

    float acc[4][4][4];
#pragma unroll
    for (int i = 0; i < 4; i++)
#pragma unroll
        for (int j = 0; j < 4; j++)
#pragma unroll
            for (int q = 0; q < 4; q++) acc[i][j][q] = 0.f;

    const int lm = tid >> 3;  // 0..31 : row within 32-row pass
    const int lk = tid & 7;   // 0..7  : 16B segment within 32-float k-tile

    // prologue: tile 0 -> stage 0
    {
        const uint32_t bA = smem_base;
        const uint32_t bB = smem_base + MAT_BYTES;
#pragma unroll
        for (int p = 0; p < 4; p++) {
            const int m = lm + 32 * p;
            const uint32_t so = (uint32_t)(m * PADF + lk * 4) * 4u;
            cp16(bA + so, Abase + (size_t)m * NH + lk * 4);
            cp16(bB + so, Bbase + (size_t)m * NH + lk * 4);
        }
        cp_commit();
    }

    for (int t = 0; t < NTILES; t++) {
        if (t + 1 < NTILES) {
            // issue next tile into other stage (its last readers finished at
            // t-1 and were closed by the trailing sync of iteration t-1)
            const uint32_t bA = smem_base + (uint32_t)((t + 1) & 1) * STAGE_BYTES;
            const uint32_t bB = bA + MAT_BYTES;
            const int k0 = (t + 1) * KT;
#pragma unroll
            for (int p = 0; p < 4; p++) {
                const int m = lm + 32 * p;
                const uint32_t so = (uint32_t)(m * PADF + lk * 4) * 4u;
                cp16(bA + so, Abase + (size_t)m * NH + k0 + lk * 4);
                cp16(bB + so, Bbase + (size_t)m * NH + k0 + lk * 4);
            }
            cp_commit();
            cp_wait<1>();   // tile t's group complete (next stays in flight)
        } else {
            cp_wait<0>();
        }
        __syncthreads();    // tile t visible to all warps

        const float* As = (const float*)(dsm + (t & 1) * STAGE_BYTES);
        const float* Bs = As + 128 * PADF;

#pragma unroll
        for (int ks = 0; ks < KT; ks += 8) {
            uint32_t bf[4][2];
#pragma unroll
            for (int j = 0; j < 4; j++) {
                const float* bp = &Bs[(wc * 32 + j * 8 + g) * PADF + ks + tg];
                bf[j][0] = __float_as_uint(bp[0]);
                bf[j][1] = __float_as_uint(bp[4]);
            }
#pragma unroll
            for (int i = 0; i < 4; i++) {
                const float* ap0 = &As[(wr * 64 + i * 16 + g) * PADF + ks + tg];
                const float* ap1 = ap0 + 8 * PADF;
                const uint32_t a0 = __float_as_uint(ap0[0]);
                const uint32_t a1 = __float_as_uint(ap1[0]);
                const uint32_t a2 = __float_as_uint(ap0[4]);
                const uint32_t a3 = __float_as_uint(ap1[4]);
#pragma unroll
                for (int j = 0; j < 4; j++)
                    mma_tf32(acc[i][j], a0, a1, a2, a3, bf[j][0], bf[j][1]);
            }
        }
        __syncthreads();    // close reads of tile t before its stage is reused
    }

    // ---- fused masked row-max (over cols, bias m2b) ----
    // D frag mapping: d0:(g, 2tg) d1:(g, 2tg+1) d2:(g+8, 2tg) d3:(g+8, 2tg+1)
#pragma unroll
    for (int i = 0; i < 4; i++) {
        float r0 = -3e30f, r1 = -3e30f;
#pragma unroll
        for (int j = 0; j < 4; j++) {
            const int c0 = wc * 32 + j * 8 + 2 * tg;
            const float b0 = m2b[c0], b1 = m2b[c0 + 1];
            r0 = fmaxf(r0, fmaxf(acc[i][j][0] + b0, acc[i][j][1] + b1));
            r1 = fmaxf(r1, fmaxf(acc[i][j][2] + b0, acc[i][j][3] + b1));
        }
        r0 = shfl_max(shfl_max(r0, 1), 2);  // reduce over tg lanes
        r1 = shfl_max(shfl_max(r1, 1), 2);
        if (tg == 0) {
            rowp[(wr * 64 + i * 16 + g) * 4 + wc] = r0;
            rowp[(wr * 64 + i * 16 + g + 8) * 4 + wc] = r1;
        }
    }

    // ---- fused masked col-max (over rows, bias m1b) ----
#pragma unroll
    for (int j = 0; j < 4; j++) {
        float c0m = -3e30f, c1m = -3e30f;
#pragma unroll
        for (int i = 0; i < 4; i++) {
            const int r0i = wr * 64 + i * 16 + g;
            const float bb0 = m1b[r0i], bb1 = m1b[r0i + 8];
            c0m = fmaxf(c0m, fmaxf(acc[i][j][0] + bb0, acc[i][j][2] + bb1));
            c1m = fmaxf(c1m, fmaxf(acc[i][j][1] + bb0, acc[i][j][3] + bb1));
        }
        c0m = shfl_max(shfl_max(shfl_max(c0m, 4), 8), 16);  // reduce over g
        c1m = shfl_max(shfl_max(shfl_max(c1m, 4), 8), 16);
        if (g == 0) {
            colp[(wc * 32 + j * 8 + 2 * tg) * 2 + wr] = c0m;
            colp[(wc * 32 + j * 8 + 2 * tg + 1) * 2 + wr] = c1m;
        }
    }
    __syncthreads();

    // ---- finish maxes, masked mean contributions ----
    float val;
    {
        const int r = tid & 127;
        float mx;
        const float* mv;
        if (tid < 128) {
            mx = fmaxf(fmaxf(rowp[r * 4 + 0], rowp[r * 4 + 1]),
                       fmaxf(rowp[r * 4 + 2], rowp[r * 4 + 3]));
            mv = m1raw;
        } else {
            mx = fmaxf(colp[r * 2 + 0], colp[r * 2 + 1]);
            mv = m2raw;
        }
        float cnt = 0.f;
#pragma unroll 8
        for (int q = 0; q < 128; q++) cnt += mv[q];
        val = mv[r] * (mx / cnt) * 0.5f;
    }

#pragma unroll
    for (int o = 16; o > 0; o >>= 1) val += __shfl_xor_sync(0xffffffffu, val, o);
    if ((tid & 31) == 0) rbuf[tid >> 5] = val;
    __syncthreads();
    if (tid == 0) {
        float s = 0.f;
#pragma unroll
        for (int i = 0; i < 8; i++) s += rbuf[i];
        out[a * NB2 + b] = s;
    }
}

// ---------------------------------------------------------------------------
extern "C" void kernel_launch(void* const* d_in, const int* in_sizes, int n_in,
                              void* d_out, int out_size) {
    const float* x1 = (const float*)d_in[0];
    const int* mask1 = (const int*)d_in[1];
    const float* x2 = (const float*)d_in[2];
    const int* mask2 = (const int*)d_in[3];
    float* out = (float*)d_out;

    cudaFuncSetAttribute(pair_kernel,
                         cudaFuncAttributeMaxDynamicSharedMemorySize,
                         DSMEM_TOTAL);

    normalize_kernel<<<dim3(NB1 * NS1, 2), 256>>>(x1, x2);
    pair_kernel<<<dim3(NB1, NB2), 256, DSMEM_TOTAL>>>(mask1, mask2, out);
}